// round 11
// baseline (speedup 1.0000x reference)
#include <cuda_runtime.h>
#define DEV __device__ __forceinline__
namespace {
typedef unsigned long long u64;
constexpr int NB=8192, NBT=64, NT=256, WS=200;

// ---- activation region (union: encoder ping-pong vs rollout U/A0/A1) ----
constexpr int O_U  = 0;              // rollout: 96x68 (s:0-15, x:16-23, e:24-31, H:32-95)
constexpr int O_A0 = 96*68;
constexpr int O_A1 = O_A0+64*68;
constexpr int HXSZ = 72*68;          // encoder buf: H(0-63) + X(64-71)
constexpr int O_P  = O_A1+64*68;     // 2 x 8x68 stat partials
constexpr int O_MNR= O_P+2*8*68;
constexpr int O_CMD= O_MNR+128;
constexpr int O_OHS= O_CMD+4*68;
constexpr int O_W  = O_OHS+8*68;
// encoder union
constexpr int E_W=O_W, E_B=E_W+72*WS;
// rollout union
constexpr int C_W=O_W, C_B=C_W+96*WS;
constexpr int W0H=C_B+256, W0XE=W0H+64*68, W0B=W0XE+16*68;
constexpr int PWt=W0B+64, PBo=PWt+3*64*68;
constexpr int C1o=PBo+192, C2o=C1o+192;
constexpr int WOo=C2o+192, WOBo=WOo+256, AMo=WOBo+8, BMo=AMo+256, CMs=BMo+64;
constexpr int SMF=CMs+128;
constexpr size_t SMEMB=(size_t)SMF*4;
constexpr size_t OFF_CMD=(size_t)NB*1600;
constexpr size_t OFF_ST =OFF_CMD+(size_t)NB*796;

DEV float sigm(float v){ return __fdividef(1.0f,1.0f+__expf(-v)); }
DEV float tanh_f(float v){ return 1.0f-__fdividef(2.0f,1.0f+__expf(2.0f*v)); }

// pack (x,x) into a b64 register pair (one mov)
DEV u64 dup2(float x){ u64 r; asm("mov.b64 %0,{%1,%1};" : "=l"(r) : "f"(x)); return r; }
// in-place packed fma: acc = w*h + acc, no operand marshalling
DEV void fma2(u64& acc, u64 w, u64 h){
  asm("fma.rn.f32x2 %0,%1,%2,%0;" : "+l"(acc) : "l"(w), "l"(h));
}
DEV float2 unp(u64 a){ float2 f; asm("mov.b64 {%0,%1},%2;" : "=f"(f.x),"=f"(f.y) : "l"(a)); return f; }
DEV void zu(u64(&A)[4][2]){
#pragma unroll
  for(int c=0;c<4;c++){ A[c][0]=0ull; A[c][1]=0ull; }
}
DEV float gat(const u64(&A)[4][2],int c,int r){
  float2 f=unp(A[c][r>>1]); return (r&1)?f.y:f.x;
}

template<int NK>
DEV void gemm3(u64(&aR)[4][2],u64(&aZ)[4][2],u64(&aN)[4][2],
               const float* WT,const float* Xs,int rg4,int cg4){
#pragma unroll 4
  for(int k=0;k<NK;k++){
    float4 hv=*(const float4*)(Xs+k*68+cg4);
    u64 hd[4]={dup2(hv.x),dup2(hv.y),dup2(hv.z),dup2(hv.w)};
    const float* wr=WT+k*WS+rg4;
    ulonglong2 w0=*(const ulonglong2*)wr;
    ulonglong2 w1=*(const ulonglong2*)(wr+64);
    ulonglong2 w2=*(const ulonglong2*)(wr+128);
#pragma unroll
    for(int c=0;c<4;c++){
      fma2(aR[c][0],w0.x,hd[c]); fma2(aR[c][1],w0.y,hd[c]);
      fma2(aZ[c][0],w1.x,hd[c]); fma2(aZ[c][1],w1.y,hd[c]);
      fma2(aN[c][0],w2.x,hd[c]); fma2(aN[c][1],w2.y,hd[c]);
    }
  }
}
template<int NK>
DEV void gemm1(u64(&A)[4][2],const float* WT,const float* Xs,int rg4,int cg4){
#pragma unroll 4
  for(int k=0;k<NK;k++){
    float4 hv=*(const float4*)(Xs+k*68+cg4);
    u64 hd[4]={dup2(hv.x),dup2(hv.y),dup2(hv.z),dup2(hv.w)};
    ulonglong2 w=*(const ulonglong2*)(WT+k*68+rg4);
#pragma unroll
    for(int c=0;c<4;c++){ fma2(A[c][0],w.x,hd[c]); fma2(A[c][1],w.y,hd[c]); }
  }
}

DEV void gru_post(const float* sm,int Bb,const float* hb,int rg4,int cg4,
    u64(&aR)[4][2],u64(&aZ)[4][2],u64(&aI)[4][2],u64(&aH)[4][2],float4(&hn)[4]){
  float br[4],bz[4],bi[4],bh[4];
  *(float4*)br=*(const float4*)(sm+Bb+rg4);     *(float4*)bz=*(const float4*)(sm+Bb+64+rg4);
  *(float4*)bi=*(const float4*)(sm+Bb+128+rg4); *(float4*)bh=*(const float4*)(sm+Bb+192+rg4);
  float hv[4][4];
#pragma unroll
  for(int r=0;r<4;r++){
    float4 ho4=*(const float4*)(hb+(rg4+r)*68+cg4);
    float ho[4]={ho4.x,ho4.y,ho4.z,ho4.w};
#pragma unroll
    for(int c=0;c<4;c++){
      float rr=sigm(gat(aR,c,r)+br[r]), zz=sigm(gat(aZ,c,r)+bz[r]);
      float nn=tanh_f(gat(aI,c,r)+bi[r]+rr*(gat(aH,c,r)+bh[r]));
      hv[r][c]=nn+zz*(ho[c]-nn);
    }
  }
#pragma unroll
  for(int r=0;r<4;r++) hn[r]=make_float4(hv[r][0],hv[r][1],hv[r][2],hv[r][3]);
}

DEV void stat_fold(float (&vv)[4][4],float* sm,int cg4,int warp,int lane){
  float s[4],q[4];
#pragma unroll
  for(int c=0;c<4;c++){
    s[c]=vv[0][c]+vv[1][c]+vv[2][c]+vv[3][c];
    q[c]=vv[0][c]*vv[0][c]+vv[1][c]*vv[1][c]+vv[2][c]*vv[2][c]+vv[3][c]*vv[3][c];
    s[c]+=__shfl_xor_sync(0xffffffffu,s[c],16);
    q[c]+=__shfl_xor_sync(0xffffffffu,q[c],16);
  }
  if(lane<16){
    *(float4*)(sm+O_P+warp*68+cg4)=make_float4(s[0],s[1],s[2],s[3]);
    *(float4*)(sm+O_P+544+warp*68+cg4)=make_float4(q[0],q[1],q[2],q[3]);
  }
}
DEV void epi(u64(&A)[4][2],const float* bias,float* Adst,float* sm,
             int rg4,int cg4,int warp,int lane,bool stats){
  float bv[4]; *(float4*)bv=*(const float4*)(bias+rg4);
  float vv[4][4];
#pragma unroll
  for(int r=0;r<4;r++)
#pragma unroll
    for(int c=0;c<4;c++) vv[r][c]=fmaxf(gat(A,c,r)+bv[r],0.f);
#pragma unroll
  for(int r=0;r<4;r++) *(float4*)(Adst+(rg4+r)*68+cg4)=make_float4(vv[r][0],vv[r][1],vv[r][2],vv[r][3]);
  if(stats) stat_fold(vv,sm,cg4,warp,lane);
}
DEV void cpT(float* dst,const float* __restrict__ src,int R,int K,int ks,int tid){
  for(int i=tid;i<R*K;i+=NT){ int r=i/K,k=i-r*K; dst[k*ks+r]=src[i]; }
}
} // namespace

__global__ void __launch_bounds__(NT,1)
sysid_kernel(const float* __restrict__ obs,
             const float* __restrict__ sysA,const float* __restrict__ sysB_,const float* __restrict__ sysC,
             const float* __restrict__ rWi,const float* __restrict__ rWh,
             const float* __restrict__ rbi,const float* __restrict__ rbh,
             const float* __restrict__ cWi,const float* __restrict__ cWh,
             const float* __restrict__ cbi,const float* __restrict__ cbh,
             const float* __restrict__ mW0,const float* __restrict__ mb0,
             const float* __restrict__ mW1,const float* __restrict__ mb1,
             const float* __restrict__ pW0,const float* __restrict__ pb0,
             const float* __restrict__ lg,const float* __restrict__ lb,
             const float* __restrict__ pW,const float* __restrict__ pb,
             const float* __restrict__ wo,const float* __restrict__ wob,
             float* __restrict__ out)
{
  extern __shared__ float sm[];
  const int tid=threadIdx.x, lane=tid&31, warp=tid>>5;
  const int cg4=(lane&15)*4, rg4=(warp*2+(lane>>4))*4;
  const int b0=blockIdx.x*NBT;
  const int oc=tid>>3, oo=tid&7;
  float* A0=sm+O_A0; float* A1=sm+O_A1;
  float* Hr=sm+O_U+32*68;

  // ================= encoder weights + init =================
  cpT(sm+E_W,rWh,192,64,WS,tid);
  cpT(sm+E_W+64*WS,rWi,192,8,WS,tid);
  for(int i=tid;i<64;i+=NT){
    sm[E_B+i]=rbi[i]+rbh[i]; sm[E_B+64+i]=rbi[64+i]+rbh[64+i];
    sm[E_B+128+i]=rbi[128+i]; sm[E_B+192+i]=rbh[128+i];
  }
  for(int i=tid;i<64*68;i+=NT) sm[i]=0.f;
  sm[(64+oo)*68+oc]=obs[(size_t)(b0+oc)*1600+oo];
  sm[(64+oo)*68+oc+32]=obs[(size_t)(b0+oc+32)*1600+oo];
  __syncthreads();

  // ================= encoder GRU: 200 steps =================
#pragma unroll 1
  for(int t=0;t<200;t++){
    float* cur=sm+(t&1)*HXSZ;
    float* nxt=sm+((t+1)&1)*HXSZ;
    int tn=(t<199)?t+1:t;
    float p0=obs[(size_t)(b0+oc)*1600+tn*8+oo];
    float p1=obs[(size_t)(b0+oc+32)*1600+tn*8+oo];
    u64 aR[4][2],aZ[4][2],aI[4][2],aH[4][2];
    zu(aR);zu(aZ);zu(aI);zu(aH);
    gemm3<64>(aR,aZ,aH,sm+E_W,cur,rg4,cg4);
    gemm3<8>(aR,aZ,aI,sm+E_W+64*WS,cur+64*68,rg4,cg4);
    float4 hn[4]; gru_post(sm,E_B,cur,rg4,cg4,aR,aZ,aI,aH,hn);
#pragma unroll
    for(int r=0;r<4;r++) *(float4*)(nxt+(rg4+r)*68+cg4)=hn[r];
    nxt[(64+oo)*68+oc]=p0; nxt[(64+oo)*68+oc+32]=p1;
    __syncthreads();
  }

  // ================= init MLP =================
  for(int i=tid;i<64*72;i+=NT){ int r=i/72,k=i-r*72; sm[O_W+k*68+r]=mW0[i]; }
  sm[(64+oo)*68+oc]=obs[(size_t)(b0+oc)*1600+oo];
  sm[(64+oo)*68+oc+32]=obs[(size_t)(b0+oc+32)*1600+oo];
  __syncthreads();
  {
    u64 a[4][2]; zu(a);
    gemm1<64>(a,sm+O_W,sm,rg4,cg4);
    gemm1<8>(a,sm+O_W+64*68,sm+64*68,rg4,cg4);
#pragma unroll
    for(int r=0;r<4;r++){
      float bb=__ldg(mb0+rg4+r);
      float4 v=make_float4(tanh_f(gat(a,0,r)+bb),tanh_f(gat(a,1,r)+bb),
                           tanh_f(gat(a,2,r)+bb),tanh_f(gat(a,3,r)+bb));
      *(float4*)(A0+(rg4+r)*68+cg4)=v;
    }
  }
  __syncthreads();
  {
    int col=tid&63, rq=tid>>6;
#pragma unroll
    for(int i=0;i<4;i++){
      int r=rq*4+i;
      float acc=__ldg(mb1+r);
      for(int k=0;k<64;k++) acc=fmaf(A0[k*68+col],__ldg(mW1+r*64+k),acc);
      sm[O_U+r*68+col]=acc;
      out[OFF_ST+(size_t)(b0+col)*3200+r]=acc;
    }
    for(int i=tid;i<64*68;i+=NT) Hr[i]=0.f;
    sm[O_U+(16+oo)*68+oc]=obs[(size_t)(b0+oc)*1600+8+oo];
    sm[O_U+(16+oo)*68+oc+32]=obs[(size_t)(b0+oc+32)*1600+8+oo];
  }
  // ---- rollout weights ----
  cpT(sm+C_W,cWi,192,32,WS,tid);
  cpT(sm+C_W+32*WS,cWh,192,64,WS,tid);
  for(int i=tid;i<64;i+=NT){
    sm[C_B+i]=cbi[i]+cbh[i]; sm[C_B+64+i]=cbi[64+i]+cbh[64+i];
    sm[C_B+128+i]=cbi[128+i]; sm[C_B+192+i]=cbh[128+i];
  }
  for(int i=tid;i<64*80;i+=NT){ int r=i/80,k=i-r*80;
    if(k<64) sm[W0H+k*68+r]=pW0[i]; else sm[W0XE+(k-64)*68+r]=pW0[i]; }
  for(int i=tid;i<64;i+=NT) sm[W0B+i]=pb0[i];
  for(int i=tid;i<12288;i+=NT){ int li=i>>12,rem=i&4095,r=rem>>6,k=rem&63;
    sm[PWt+li*4352+k*68+r]=pW[i]; }
  for(int i=tid;i<256;i+=NT){ sm[WOo+i]=wo[i]; sm[AMo+i]=sysA[i]; }
  if(tid<4) sm[WOBo+tid]=wob[tid];
  for(int i=tid;i<64;i+=NT) sm[BMo+i]=sysB_[i];
  for(int i=tid;i<128;i+=NT) sm[CMs+i]=sysC[i];
  __syncthreads();
  // LN fold constants
  if(tid<192){
    int li=tid>>6, r=tid&63;
    float c1=0.f,c2=0.f;
    for(int k=0;k<64;k++){
      float w=sm[PWt+li*4352+k*68+r];
      c1=fmaf(w,__ldg(lb+li*64+k),c1);
      c2=fmaf(w,__ldg(lg+li*64+k),c2);
    }
    sm[C1o+tid]=c1+__ldg(pb+tid);
    sm[C2o+tid]=c2;
  }
  __syncthreads();
  for(int i=tid;i<12288;i+=NT){ int li=i>>12,rem=i&4095,k=rem>>6,r=rem&63;
    sm[PWt+li*4352+k*68+r]*=__ldg(lg+li*64+k); }
  __syncthreads();

  // ================= rollout: 199 steps =================
  const int s1row=tid>>5, s1c=lane*2;
#pragma unroll 1
  for(int t=1;t<200;t++){
    int tn=(t<199)?t+1:t;
    float p0=obs[(size_t)(b0+oc)*1600+tn*8+oo];
    float p1=obs[(size_t)(b0+oc+32)*1600+tn*8+oo];

    // S1: oh = C@s ; e = x - oh
    {
      float2 o=make_float2(0.f,0.f);
#pragma unroll
      for(int k=0;k<16;k++){
        float cw=sm[CMs+s1row*16+k];
        float2 sv=*(const float2*)(sm+O_U+k*68+s1c);
        o.x=fmaf(cw,sv.x,o.x); o.y=fmaf(cw,sv.y,o.y);
      }
      float2 xv=*(const float2*)(sm+O_U+(16+s1row)*68+s1c);
      *(float2*)(sm+O_U+(24+s1row)*68+s1c)=make_float2(xv.x-o.x,xv.y-o.y);
      *(float2*)(sm+O_OHS+s1row*68+s1c)=o;
    }
    __syncthreads();
    if(tid>=64&&tid<128){
      int col=tid-64;
      float v[8];
#pragma unroll
      for(int r=0;r<8;r++) v[r]=sm[O_OHS+r*68+col];
      float* dst=out+(size_t)(b0+col)*1600+(size_t)(t-1)*8;
      *(float4*)dst=make_float4(v[0],v[1],v[2],v[3]);
      *(float4*)(dst+4)=make_float4(v[4],v[5],v[6],v[7]);
    }

    // S2: GRU on [U(32); H(64)]
    {
      u64 aR[4][2],aZ[4][2],aI[4][2],aH[4][2];
      zu(aR);zu(aZ);zu(aI);zu(aH);
      gemm3<32>(aR,aZ,aI,sm+C_W,sm+O_U,rg4,cg4);
      gemm3<64>(aR,aZ,aH,sm+C_W+32*WS,Hr,rg4,cg4);
      float4 hn[4]; gru_post(sm,C_B,Hr,rg4,cg4,aR,aZ,aI,aH,hn);
      __syncthreads();
#pragma unroll
      for(int r=0;r<4;r++) *(float4*)(Hr+(rg4+r)*68+cg4)=hn[r];
    }
    __syncthreads();

    // S3: W0 ([H;x,e]) -> relu (+stats for LN0)
    {
      u64 a[4][2]; zu(a);
      gemm1<64>(a,sm+W0H,Hr,rg4,cg4);
      gemm1<16>(a,sm+W0XE,sm+O_U+16*68,rg4,cg4);
      epi(a,sm+W0B,A0,sm,rg4,cg4,warp,lane,true);
    }
    __syncthreads();

    // S4: 3 x fused (LN -> linear -> relu) via prescaled weights
    float* cur=A0; float* nxt=A1;
#pragma unroll 1
    for(int li=0;li<3;li++){
      float sS[4]={0.f,0.f,0.f,0.f}, sQ[4]={0.f,0.f,0.f,0.f};
#pragma unroll
      for(int g=0;g<8;g++){
        float4 a4=*(const float4*)(sm+O_P+g*68+cg4);
        float4 b4=*(const float4*)(sm+O_P+544+g*68+cg4);
        sS[0]+=a4.x; sS[1]+=a4.y; sS[2]+=a4.z; sS[3]+=a4.w;
        sQ[0]+=b4.x; sQ[1]+=b4.y; sQ[2]+=b4.z; sQ[3]+=b4.w;
      }
      float mM[4],rS[4];
#pragma unroll
      for(int c=0;c<4;c++){
        mM[c]=sS[c]*(1.f/64.f);
        rS[c]=rsqrtf(fmaf(-mM[c],mM[c],sQ[c]*(1.f/64.f))+1e-5f);
      }
      if(li<2) __syncthreads();
      u64 a[4][2]; zu(a);
      gemm1<64>(a,sm+PWt+li*4352,cur,rg4,cg4);
      float4 c14=*(const float4*)(sm+C1o+li*64+rg4);
      float4 c24=*(const float4*)(sm+C2o+li*64+rg4);
      float c1v[4]={c14.x,c14.y,c14.z,c14.w}, c2v[4]={c24.x,c24.y,c24.z,c24.w};
      float vv[4][4];
#pragma unroll
      for(int r=0;r<4;r++)
#pragma unroll
        for(int c=0;c<4;c++){
          float v=fmaf(rS[c],gat(a,c,r)-mM[c]*c2v[r],c1v[r]);
          vv[r][c]=fmaxf(v,0.f);
        }
#pragma unroll
      for(int r=0;r<4;r++) *(float4*)(nxt+(rg4+r)*68+cg4)=make_float4(vv[r][0],vv[r][1],vv[r][2],vv[r][3]);
      if(li<2) stat_fold(vv,sm,cg4,warp,lane);
      __syncthreads();
      float* tp=cur; cur=nxt; nxt=tp;
    }

    // S5: cmd = x@Wout.T + b
    {
      int col=tid&63, r=tid>>6;
      float acc=sm[WOBo+r];
      for(int k=0;k<64;k++) acc=fmaf(cur[k*68+col],sm[WOo+r*64+k],acc);
      sm[O_CMD+r*68+col]=acc;
    }
    __syncthreads();

    // S6: ns = s@A.T + cmd@B.T, mask, advance
    {
      int col=tid&63, rq=tid>>6;
      float ns[4];
#pragma unroll
      for(int i=0;i<4;i++){
        int r=rq*4+i; float a=0.f;
#pragma unroll
        for(int k=0;k<16;k++) a=fmaf(sm[AMo+r*16+k],sm[O_U+k*68+col],a);
#pragma unroll
        for(int k=0;k<4;k++) a=fmaf(sm[BMo+r*4+k],sm[O_CMD+k*68+col],a);
        ns[i]=(a>-100.f&&a<100.f)?a:0.f;
      }
      __syncthreads();
#pragma unroll
      for(int i=0;i<4;i++) sm[O_U+(rq*4+i)*68+col]=ns[i];
      sm[O_U+(16+oo)*68+oc]=p0; sm[O_U+(16+oo)*68+oc+32]=p1;
    }
    __syncthreads();
    if(tid<64){
      int col=tid;
      float* ds=out+OFF_ST+(size_t)(b0+col)*3200+(size_t)t*16;
#pragma unroll
      for(int q=0;q<4;q++){
        float4 v=make_float4(sm[O_U+(q*4+0)*68+col],sm[O_U+(q*4+1)*68+col],
                             sm[O_U+(q*4+2)*68+col],sm[O_U+(q*4+3)*68+col]);
        *(float4*)(ds+q*4)=v;
      }
      float4 cv=make_float4(sm[O_CMD+0*68+col],sm[O_CMD+1*68+col],
                            sm[O_CMD+2*68+col],sm[O_CMD+3*68+col]);
      *(float4*)(out+OFF_CMD+(size_t)(b0+col)*796+(size_t)(t-1)*4)=cv;
    }
  }

  // tail: obs_hat[199] = states[199]@C.T
  {
    float2 o=make_float2(0.f,0.f);
#pragma unroll
    for(int k=0;k<16;k++){
      float cw=sm[CMs+s1row*16+k];
      float2 sv=*(const float2*)(sm+O_U+k*68+s1c);
      o.x=fmaf(cw,sv.x,o.x); o.y=fmaf(cw,sv.y,o.y);
    }
    out[(size_t)(b0+s1c)*1600+1592+s1row]=o.x;
    out[(size_t)(b0+s1c+1)*1600+1592+s1row]=o.y;
  }
}

extern "C" void kernel_launch(void* const* d_in, const int* in_sizes, int n_in,
                              void* d_out, int out_size) {
  (void)in_sizes;(void)n_in;(void)out_size;
  cudaFuncSetAttribute(sysid_kernel,cudaFuncAttributeMaxDynamicSharedMemorySize,(int)SMEMB);
  sysid_kernel<<<NB/NBT,NT,SMEMB>>>(
    (const float*)d_in[0],(const float*)d_in[1],(const float*)d_in[2],(const float*)d_in[3],
    (const float*)d_in[4],(const float*)d_in[5],(const float*)d_in[6],(const float*)d_in[7],
    (const float*)d_in[8],(const float*)d_in[9],(const float*)d_in[10],(const float*)d_in[11],
    (const float*)d_in[12],(const float*)d_in[13],(const float*)d_in[14],(const float*)d_in[15],
    (const float*)d_in[16],(const float*)d_in[17],(const float*)d_in[18],(const float*)d_in[19],
    (const float*)d_in[20],(const float*)d_in[21],(const float*)d_in[22],(const float*)d_in[23],
    (float*)d_out);
}

// round 12
// speedup vs baseline: 1.0735x; 1.0735x over previous
#include <cuda_runtime.h>
#define DEV __device__ __forceinline__
namespace {
constexpr int NB=8192, NBT=64, NT=256, WS=200;

// ---- activation region (union: encoder ping-pong vs rollout U/A0/A1) ----
constexpr int O_U  = 0;              // rollout: 96x68 (s:0-15, x:16-23, e:24-31, H:32-95)
constexpr int O_A0 = 96*68;
constexpr int O_A1 = O_A0+64*68;
constexpr int HXSZ = 72*68;          // encoder buf: H(0-63) + X(64-71)
constexpr int O_P  = O_A1+64*68;     // 2 x 8x68 stat partials
constexpr int O_MNR= O_P+2*8*68;
constexpr int O_CMD= O_MNR+128;
constexpr int O_OHS= O_CMD+4*68;
constexpr int O_W  = O_OHS+8*68;
// encoder union
constexpr int E_W=O_W, E_B=E_W+72*WS;
// rollout union
constexpr int C_W=O_W, C_B=C_W+96*WS;
constexpr int W0H=C_B+256, W0XE=W0H+64*68, W0B=W0XE+16*68;
constexpr int PWt=W0B+64, PBo=PWt+3*64*68;
constexpr int C1o=PBo+192, C2o=C1o+192;
constexpr int WOo=C2o+192, WOBo=WOo+256, AMo=WOBo+8, BMo=AMo+256, CMs=BMo+64;
constexpr int SMF=CMs+128;
constexpr size_t SMEMB=(size_t)SMF*4;
constexpr size_t OFF_CMD=(size_t)NB*1600;
constexpr size_t OFF_ST =OFF_CMD+(size_t)NB*796;

DEV float sigm(float v){ return __fdividef(1.0f,1.0f+__expf(-v)); }
DEV float tanh_f(float v){ return 1.0f-__fdividef(2.0f,1.0f+__expf(2.0f*v)); }

DEV float2 f2fma(float2 a,float2 b,float2 c){
  float2 d;
  asm("{\n\t.reg .b64 ra,rb,rc;\n\t"
      "mov.b64 ra,{%2,%3};\n\tmov.b64 rb,{%4,%5};\n\tmov.b64 rc,{%6,%7};\n\t"
      "fma.rn.f32x2 rc,ra,rb,rc;\n\tmov.b64 {%0,%1},rc;\n\t}"
      : "=f"(d.x),"=f"(d.y)
      : "f"(a.x),"f"(a.y),"f"(b.x),"f"(b.y),"f"(c.x),"f"(c.y));
  return d;
}
DEV void z2(float2(&A)[4][2]){
#pragma unroll
  for(int c=0;c<4;c++){ A[c][0]=make_float2(0.f,0.f); A[c][1]=make_float2(0.f,0.f); }
}
template<int NK>
DEV void gemm3(float2(&aR)[4][2],float2(&aZ)[4][2],float2(&aN)[4][2],
               const float* WT,const float* Xs,int rg4,int cg4){
#pragma unroll 8
  for(int k=0;k<NK;k++){
    float4 hv=*(const float4*)(Xs+k*68+cg4);
    float2 hd[4]={{hv.x,hv.x},{hv.y,hv.y},{hv.z,hv.z},{hv.w,hv.w}};
    const float* wr=WT+k*WS+rg4;
    float4 w0=*(const float4*)wr, w1=*(const float4*)(wr+64), w2=*(const float4*)(wr+128);
    float2 w0a={w0.x,w0.y},w0b={w0.z,w0.w},w1a={w1.x,w1.y},w1b={w1.z,w1.w},w2a={w2.x,w2.y},w2b={w2.z,w2.w};
#pragma unroll
    for(int c=0;c<4;c++){
      aR[c][0]=f2fma(w0a,hd[c],aR[c][0]); aR[c][1]=f2fma(w0b,hd[c],aR[c][1]);
      aZ[c][0]=f2fma(w1a,hd[c],aZ[c][0]); aZ[c][1]=f2fma(w1b,hd[c],aZ[c][1]);
      aN[c][0]=f2fma(w2a,hd[c],aN[c][0]); aN[c][1]=f2fma(w2b,hd[c],aN[c][1]);
    }
  }
}
template<int NK>
DEV void gemm1(float2(&A)[4][2],const float* WT,const float* Xs,int rg4,int cg4){
#pragma unroll 8
  for(int k=0;k<NK;k++){
    float4 hv=*(const float4*)(Xs+k*68+cg4);
    float2 hd[4]={{hv.x,hv.x},{hv.y,hv.y},{hv.z,hv.z},{hv.w,hv.w}};
    float4 w=*(const float4*)(WT+k*68+rg4);
    float2 wa={w.x,w.y},wb={w.z,w.w};
#pragma unroll
    for(int c=0;c<4;c++){ A[c][0]=f2fma(wa,hd[c],A[c][0]); A[c][1]=f2fma(wb,hd[c],A[c][1]); }
  }
}
DEV float gat(const float2(&A)[4][2],int c,int r){ return (r&1)?A[c][r>>1].y:A[c][r>>1].x; }

DEV void gru_post(const float* sm,int Bb,const float* hb,int rg4,int cg4,
    float2(&aR)[4][2],float2(&aZ)[4][2],float2(&aI)[4][2],float2(&aH)[4][2],float4(&hn)[4]){
  float br[4],bz[4],bi[4],bh[4];
  *(float4*)br=*(const float4*)(sm+Bb+rg4);     *(float4*)bz=*(const float4*)(sm+Bb+64+rg4);
  *(float4*)bi=*(const float4*)(sm+Bb+128+rg4); *(float4*)bh=*(const float4*)(sm+Bb+192+rg4);
  float hv[4][4];
#pragma unroll
  for(int r=0;r<4;r++){
    float4 ho4=*(const float4*)(hb+(rg4+r)*68+cg4);
    float ho[4]={ho4.x,ho4.y,ho4.z,ho4.w};
#pragma unroll
    for(int c=0;c<4;c++){
      float rr=sigm(gat(aR,c,r)+br[r]), zz=sigm(gat(aZ,c,r)+bz[r]);
      float nn=tanh_f(gat(aI,c,r)+bi[r]+rr*(gat(aH,c,r)+bh[r]));
      hv[r][c]=nn+zz*(ho[c]-nn);
    }
  }
#pragma unroll
  for(int r=0;r<4;r++) hn[r]=make_float4(hv[r][0],hv[r][1],hv[r][2],hv[r][3]);
}

DEV void stat_fold(float (&vv)[4][4],float* sm,int cg4,int warp,int lane){
  float s[4],q[4];
#pragma unroll
  for(int c=0;c<4;c++){
    s[c]=vv[0][c]+vv[1][c]+vv[2][c]+vv[3][c];
    q[c]=vv[0][c]*vv[0][c]+vv[1][c]*vv[1][c]+vv[2][c]*vv[2][c]+vv[3][c]*vv[3][c];
    s[c]+=__shfl_xor_sync(0xffffffffu,s[c],16);
    q[c]+=__shfl_xor_sync(0xffffffffu,q[c],16);
  }
  if(lane<16){
    *(float4*)(sm+O_P+warp*68+cg4)=make_float4(s[0],s[1],s[2],s[3]);
    *(float4*)(sm+O_P+544+warp*68+cg4)=make_float4(q[0],q[1],q[2],q[3]);
  }
}
DEV void epi(float2(&A)[4][2],const float* bias,float* Adst,float* sm,
             int rg4,int cg4,int warp,int lane,bool stats){
  float bv[4]; *(float4*)bv=*(const float4*)(bias+rg4);
  float vv[4][4];
#pragma unroll
  for(int r=0;r<4;r++)
#pragma unroll
    for(int c=0;c<4;c++) vv[r][c]=fmaxf(gat(A,c,r)+bv[r],0.f);
#pragma unroll
  for(int r=0;r<4;r++) *(float4*)(Adst+(rg4+r)*68+cg4)=make_float4(vv[r][0],vv[r][1],vv[r][2],vv[r][3]);
  if(stats) stat_fold(vv,sm,cg4,warp,lane);
}
DEV void cpT(float* dst,const float* __restrict__ src,int R,int K,int ks,int tid){
  for(int i=tid;i<R*K;i+=NT){ int r=i/K,k=i-r*K; dst[k*ks+r]=src[i]; }
}
} // namespace

__global__ void __launch_bounds__(NT,1)
sysid_kernel(const float* __restrict__ obs,
             const float* __restrict__ sysA,const float* __restrict__ sysB_,const float* __restrict__ sysC,
             const float* __restrict__ rWi,const float* __restrict__ rWh,
             const float* __restrict__ rbi,const float* __restrict__ rbh,
             const float* __restrict__ cWi,const float* __restrict__ cWh,
             const float* __restrict__ cbi,const float* __restrict__ cbh,
             const float* __restrict__ mW0,const float* __restrict__ mb0,
             const float* __restrict__ mW1,const float* __restrict__ mb1,
             const float* __restrict__ pW0,const float* __restrict__ pb0,
             const float* __restrict__ lg,const float* __restrict__ lb,
             const float* __restrict__ pW,const float* __restrict__ pb,
             const float* __restrict__ wo,const float* __restrict__ wob,
             float* __restrict__ out)
{
  extern __shared__ float sm[];
  const int tid=threadIdx.x, lane=tid&31, warp=tid>>5;
  const int cg4=(lane&15)*4, rg4=(warp*2+(lane>>4))*4;
  const int b0=blockIdx.x*NBT;
  const int oc=tid>>3, oo=tid&7;
  float* A0=sm+O_A0; float* A1=sm+O_A1;
  float* Hr=sm+O_U+32*68;

  // ================= encoder weights + init =================
  cpT(sm+E_W,rWh,192,64,WS,tid);
  cpT(sm+E_W+64*WS,rWi,192,8,WS,tid);
  for(int i=tid;i<64;i+=NT){
    sm[E_B+i]=rbi[i]+rbh[i]; sm[E_B+64+i]=rbi[64+i]+rbh[64+i];
    sm[E_B+128+i]=rbi[128+i]; sm[E_B+192+i]=rbh[128+i];
  }
  for(int i=tid;i<64*68;i+=NT) sm[i]=0.f;
  sm[(64+oo)*68+oc]=obs[(size_t)(b0+oc)*1600+oo];
  sm[(64+oo)*68+oc+32]=obs[(size_t)(b0+oc+32)*1600+oo];
  __syncthreads();

  // ================= encoder GRU: 200 steps =================
#pragma unroll 1
  for(int t=0;t<200;t++){
    float* cur=sm+(t&1)*HXSZ;
    float* nxt=sm+((t+1)&1)*HXSZ;
    int tn=(t<199)?t+1:t;
    float p0=obs[(size_t)(b0+oc)*1600+tn*8+oo];
    float p1=obs[(size_t)(b0+oc+32)*1600+tn*8+oo];
    float2 aR[4][2],aZ[4][2],aI[4][2],aH[4][2];
    z2(aR);z2(aZ);z2(aI);z2(aH);
    gemm3<64>(aR,aZ,aH,sm+E_W,cur,rg4,cg4);
    gemm3<8>(aR,aZ,aI,sm+E_W+64*WS,cur+64*68,rg4,cg4);
    float4 hn[4]; gru_post(sm,E_B,cur,rg4,cg4,aR,aZ,aI,aH,hn);
#pragma unroll
    for(int r=0;r<4;r++) *(float4*)(nxt+(rg4+r)*68+cg4)=hn[r];
    nxt[(64+oo)*68+oc]=p0; nxt[(64+oo)*68+oc+32]=p1;
    __syncthreads();
  }

  // ================= init MLP =================
  for(int i=tid;i<64*72;i+=NT){ int r=i/72,k=i-r*72; sm[O_W+k*68+r]=mW0[i]; }
  sm[(64+oo)*68+oc]=obs[(size_t)(b0+oc)*1600+oo];
  sm[(64+oo)*68+oc+32]=obs[(size_t)(b0+oc+32)*1600+oo];
  __syncthreads();
  {
    float2 a[4][2]; z2(a);
    gemm1<64>(a,sm+O_W,sm,rg4,cg4);
    gemm1<8>(a,sm+O_W+64*68,sm+64*68,rg4,cg4);
#pragma unroll
    for(int r=0;r<4;r++){
      float bb=__ldg(mb0+rg4+r);
      float4 v=make_float4(tanh_f(gat(a,0,r)+bb),tanh_f(gat(a,1,r)+bb),
                           tanh_f(gat(a,2,r)+bb),tanh_f(gat(a,3,r)+bb));
      *(float4*)(A0+(rg4+r)*68+cg4)=v;
    }
  }
  __syncthreads();
  {
    int col=tid&63, rq=tid>>6;
#pragma unroll
    for(int i=0;i<4;i++){
      int r=rq*4+i;
      float acc=__ldg(mb1+r);
      for(int k=0;k<64;k++) acc=fmaf(A0[k*68+col],__ldg(mW1+r*64+k),acc);
      sm[O_U+r*68+col]=acc;
      out[OFF_ST+(size_t)(b0+col)*3200+r]=acc;
    }
    for(int i=tid;i<64*68;i+=NT) Hr[i]=0.f;
    sm[O_U+(16+oo)*68+oc]=obs[(size_t)(b0+oc)*1600+8+oo];
    sm[O_U+(16+oo)*68+oc+32]=obs[(size_t)(b0+oc+32)*1600+8+oo];
  }
  // ---- rollout weights ----
  cpT(sm+C_W,cWi,192,32,WS,tid);
  cpT(sm+C_W+32*WS,cWh,192,64,WS,tid);
  for(int i=tid;i<64;i+=NT){
    sm[C_B+i]=cbi[i]+cbh[i]; sm[C_B+64+i]=cbi[64+i]+cbh[64+i];
    sm[C_B+128+i]=cbi[128+i]; sm[C_B+192+i]=cbh[128+i];
  }
  for(int i=tid;i<64*80;i+=NT){ int r=i/80,k=i-r*80;
    if(k<64) sm[W0H+k*68+r]=pW0[i]; else sm[W0XE+(k-64)*68+r]=pW0[i]; }
  for(int i=tid;i<64;i+=NT) sm[W0B+i]=pb0[i];
  for(int i=tid;i<12288;i+=NT){ int li=i>>12,rem=i&4095,r=rem>>6,k=rem&63;
    sm[PWt+li*4352+k*68+r]=pW[i]; }
  for(int i=tid;i<256;i+=NT){ sm[WOo+i]=wo[i]; sm[AMo+i]=sysA[i]; }
  if(tid<4) sm[WOBo+tid]=wob[tid];
  for(int i=tid;i<64;i+=NT) sm[BMo+i]=sysB_[i];
  for(int i=tid;i<128;i+=NT) sm[CMs+i]=sysC[i];
  __syncthreads();
  // e-fold: Wi'[s] = Wi_s - Wi_e @ C ; Wi'[x] = Wi_x + Wi_e  (GRU input 32 -> 24 dims)
  for(int i=tid;i<192*16;i+=NT){
    int m=i/192, r=i-m*192;
    float acc=sm[C_W+m*WS+r];
#pragma unroll
    for(int j=0;j<8;j++) acc=fmaf(-sm[C_W+(24+j)*WS+r], sm[CMs+j*16+m], acc);
    sm[C_W+m*WS+r]=acc;
  }
  for(int i=tid;i<192*8;i+=NT){
    int j=i/192, r=i-j*192;
    sm[C_W+(16+j)*WS+r]+=sm[C_W+(24+j)*WS+r];
  }
  // LN fold constants
  if(tid<192){
    int li=tid>>6, r=tid&63;
    float c1=0.f,c2=0.f;
    for(int k=0;k<64;k++){
      float w=sm[PWt+li*4352+k*68+r];
      c1=fmaf(w,__ldg(lb+li*64+k),c1);
      c2=fmaf(w,__ldg(lg+li*64+k),c2);
    }
    sm[C1o+tid]=c1+__ldg(pb+tid);
    sm[C2o+tid]=c2;
  }
  __syncthreads();
  for(int i=tid;i<12288;i+=NT){ int li=i>>12,rem=i&4095,k=rem>>6,r=rem&63;
    sm[PWt+li*4352+k*68+r]*=__ldg(lg+li*64+k); }
  __syncthreads();

  // ================= rollout: 199 steps =================
  const int s1row=tid>>5, s1c=lane*2;
#pragma unroll 1
  for(int t=1;t<200;t++){
    int tn=(t<199)?t+1:t;
    float p0=obs[(size_t)(b0+oc)*1600+tn*8+oo];
    float p1=obs[(size_t)(b0+oc+32)*1600+tn*8+oo];

    // S1: oh = C@s ; e = x - oh
    {
      float2 o=make_float2(0.f,0.f);
#pragma unroll
      for(int k=0;k<16;k++){
        float cw=sm[CMs+s1row*16+k];
        float2 sv=*(const float2*)(sm+O_U+k*68+s1c);
        o.x=fmaf(cw,sv.x,o.x); o.y=fmaf(cw,sv.y,o.y);
      }
      float2 xv=*(const float2*)(sm+O_U+(16+s1row)*68+s1c);
      *(float2*)(sm+O_U+(24+s1row)*68+s1c)=make_float2(xv.x-o.x,xv.y-o.y);
      *(float2*)(sm+O_OHS+s1row*68+s1c)=o;
    }
    __syncthreads();
    if(tid>=64&&tid<128){
      int col=tid-64;
      float v[8];
#pragma unroll
      for(int r=0;r<8;r++) v[r]=sm[O_OHS+r*68+col];
      float* dst=out+(size_t)(b0+col)*1600+(size_t)(t-1)*8;
      *(float4*)dst=make_float4(v[0],v[1],v[2],v[3]);
      *(float4*)(dst+4)=make_float4(v[4],v[5],v[6],v[7]);
    }

    // S2: GRU on folded [s(16); x(8)] + H(64)
    {
      float2 aR[4][2],aZ[4][2],aI[4][2],aH[4][2];
      z2(aR);z2(aZ);z2(aI);z2(aH);
      gemm3<24>(aR,aZ,aI,sm+C_W,sm+O_U,rg4,cg4);
      gemm3<64>(aR,aZ,aH,sm+C_W+32*WS,Hr,rg4,cg4);
      float4 hn[4]; gru_post(sm,C_B,Hr,rg4,cg4,aR,aZ,aI,aH,hn);
      __syncthreads();
#pragma unroll
      for(int r=0;r<4;r++) *(float4*)(Hr+(rg4+r)*68+cg4)=hn[r];
    }
    __syncthreads();

    // S3: W0 ([H;x,e]) -> relu (+stats for LN0)
    {
      float2 a[4][2]; z2(a);
      gemm1<64>(a,sm+W0H,Hr,rg4,cg4);
      gemm1<16>(a,sm+W0XE,sm+O_U+16*68,rg4,cg4);
      epi(a,sm+W0B,A0,sm,rg4,cg4,warp,lane,true);
    }
    __syncthreads();

    // S4: 3 x fused (LN -> linear -> relu) via prescaled weights
    float* cur=A0; float* nxt=A1;
#pragma unroll 1
    for(int li=0;li<3;li++){
      float sS[4]={0.f,0.f,0.f,0.f}, sQ[4]={0.f,0.f,0.f,0.f};
#pragma unroll
      for(int g=0;g<8;g++){
        float4 a4=*(const float4*)(sm+O_P+g*68+cg4);
        float4 b4=*(const float4*)(sm+O_P+544+g*68+cg4);
        sS[0]+=a4.x; sS[1]+=a4.y; sS[2]+=a4.z; sS[3]+=a4.w;
        sQ[0]+=b4.x; sQ[1]+=b4.y; sQ[2]+=b4.z; sQ[3]+=b4.w;
      }
      float mM[4],rS[4];
#pragma unroll
      for(int c=0;c<4;c++){
        mM[c]=sS[c]*(1.f/64.f);
        rS[c]=rsqrtf(fmaf(-mM[c],mM[c],sQ[c]*(1.f/64.f))+1e-5f);
      }
      if(li<2) __syncthreads();
      float2 a[4][2]; z2(a);
      gemm1<64>(a,sm+PWt+li*4352,cur,rg4,cg4);
      float4 c14=*(const float4*)(sm+C1o+li*64+rg4);
      float4 c24=*(const float4*)(sm+C2o+li*64+rg4);
      float c1v[4]={c14.x,c14.y,c14.z,c14.w}, c2v[4]={c24.x,c24.y,c24.z,c24.w};
      float vv[4][4];
#pragma unroll
      for(int r=0;r<4;r++)
#pragma unroll
        for(int c=0;c<4;c++){
          float v=fmaf(rS[c],gat(a,c,r)-mM[c]*c2v[r],c1v[r]);
          vv[r][c]=fmaxf(v,0.f);
        }
#pragma unroll
      for(int r=0;r<4;r++) *(float4*)(nxt+(rg4+r)*68+cg4)=make_float4(vv[r][0],vv[r][1],vv[r][2],vv[r][3]);
      if(li<2) stat_fold(vv,sm,cg4,warp,lane);
      __syncthreads();
      float* tp=cur; cur=nxt; nxt=tp;
    }

    // S5: cmd = x@Wout.T + b
    {
      int col=tid&63, r=tid>>6;
      float acc=sm[WOBo+r];
      for(int k=0;k<64;k++) acc=fmaf(cur[k*68+col],sm[WOo+r*64+k],acc);
      sm[O_CMD+r*68+col]=acc;
    }
    __syncthreads();

    // S6: ns = s@A.T + cmd@B.T, mask, advance
    {
      int col=tid&63, rq=tid>>6;
      float ns[4];
#pragma unroll
      for(int i=0;i<4;i++){
        int r=rq*4+i; float a=0.f;
#pragma unroll
        for(int k=0;k<16;k++) a=fmaf(sm[AMo+r*16+k],sm[O_U+k*68+col],a);
#pragma unroll
        for(int k=0;k<4;k++) a=fmaf(sm[BMo+r*4+k],sm[O_CMD+k*68+col],a);
        ns[i]=(a>-100.f&&a<100.f)?a:0.f;
      }
      __syncthreads();
#pragma unroll
      for(int i=0;i<4;i++) sm[O_U+(rq*4+i)*68+col]=ns[i];
      sm[O_U+(16+oo)*68+oc]=p0; sm[O_U+(16+oo)*68+oc+32]=p1;
    }
    __syncthreads();
    if(tid<64){
      int col=tid;
      float* ds=out+OFF_ST+(size_t)(b0+col)*3200+(size_t)t*16;
#pragma unroll
      for(int q=0;q<4;q++){
        float4 v=make_float4(sm[O_U+(q*4+0)*68+col],sm[O_U+(q*4+1)*68+col],
                             sm[O_U+(q*4+2)*68+col],sm[O_U+(q*4+3)*68+col]);
        *(float4*)(ds+q*4)=v;
      }
      float4 cv=make_float4(sm[O_CMD+0*68+col],sm[O_CMD+1*68+col],
                            sm[O_CMD+2*68+col],sm[O_CMD+3*68+col]);
      *(float4*)(out+OFF_CMD+(size_t)(b0+col)*796+(size_t)(t-1)*4)=cv;
    }
  }

  // tail: obs_hat[199] = states[199]@C.T
  {
    float2 o=make_float2(0.f,0.f);
#pragma unroll
    for(int k=0;k<16;k++){
      float cw=sm[CMs+s1row*16+k];
      float2 sv=*(const float2*)(sm+O_U+k*68+s1c);
      o.x=fmaf(cw,sv.x,o.x); o.y=fmaf(cw,sv.y,o.y);
    }
    out[(size_t)(b0+s1c)*1600+1592+s1row]=o.x;
    out[(size_t)(b0+s1c+1)*1600+1592+s1row]=o.y;
  }
}

extern "C" void kernel_launch(void* const* d_in, const int* in_sizes, int n_in,
                              void* d_out, int out_size) {
  (void)in_sizes;(void)n_in;(void)out_size;
  cudaFuncSetAttribute(sysid_kernel,cudaFuncAttributeMaxDynamicSharedMemorySize,(int)SMEMB);
  sysid_kernel<<<NB/NBT,NT,SMEMB>>>(
    (const float*)d_in[0],(const float*)d_in[1],(const float*)d_in[2],(const float*)d_in[3],
    (const float*)d_in[4],(const float*)d_in[5],(const float*)d_in[6],(const float*)d_in[7],
    (const float*)d_in[8],(const float*)d_in[9],(const float*)d_in[10],(const float*)d_in[11],
    (const float*)d_in[12],(const float*)d_in[13],(const float*)d_in[14],(const float*)d_in[15],
    (const float*)d_in[16],(const float*)d_in[17],(const float*)d_in[18],(const float*)d_in[19],
    (const float*)d_in[20],(const float*)d_in[21],(const float*)d_in[22],(const float*)d_in[23],
    (float*)d_out);
}